// round 1
// baseline (speedup 1.0000x reference)
#include <cuda_runtime.h>
#include <math.h>

// ---------------------------------------------------------------------------
// MixtureOfExperts_33844342292483 — fp32 baseline (round 0)
// B=8192, C=4, D=256, E=8, H=256, O=128, CO=512, HQ=512, AQ=18
// ---------------------------------------------------------------------------

#define B_   8192
#define C_   4
#define D_   256
#define E_   8
#define H_   256
#define O_   128
#define CO_  512
#define HQ_  512
#define AQ_  18
#define N_   (B_ * C_)            // 32768 tokens

#define TM_  64                   // tokens per CTA
#define NTHREADS_ 256

// Scratch (device globals — no allocation allowed)
__device__ float g_result[B_ * CO_];   // 16 MB
__device__ float g_out   [B_ * CO_];   // 16 MB
__device__ float g_x2    [N_ * D_];    // 32 MB
__device__ float g_hq    [B_ * HQ_];   // 16 MB
__device__ float g_s     [B_];         // gate scale per batch row

// ---------------------------------------------------------------------------
// Fused MoE forward: Out[n, 0:128] = sum_e g[n,e] * (relu(X@We1[e]+be1[e]) @ We2[e] + be2[e])
// X: N x 256. Grid: N/64 CTAs, 256 threads.
// smem: Xs[256][68] + Hs[256][68] + Ws[16384] + LG[64*8] = 51712 floats = 206848 B
// ---------------------------------------------------------------------------
#define MOE_SMEM_FLOATS (256*68 + 256*68 + 16384 + 512)
#define MOE_SMEM_BYTES  (MOE_SMEM_FLOATS * 4)

__global__ void __launch_bounds__(NTHREADS_, 1)
moe_kernel(const float* __restrict__ X,
           const float* __restrict__ We1, const float* __restrict__ be1,
           const float* __restrict__ We2, const float* __restrict__ be2,
           const float* __restrict__ Wg,  const float* __restrict__ bg,
           float* __restrict__ Out,
           const float* __restrict__ S)   // per-batch gate scale, or null (all active)
{
    extern __shared__ float sm[];
    float* Xs = sm;                    // [k=256][t=68 pad]
    float* Hs = sm + 256 * 68;         // [h=256][t=68 pad]
    float* Ws = sm + 2 * 256 * 68;     // 16384 floats (weight chunks / Wg)
    float* LG = Ws + 16384;            // [64][8] gating logits -> softmax

    const int tid  = threadIdx.x;
    const int lane = tid & 31;
    const int wid  = tid >> 5;
    const int n0   = blockIdx.x * TM_;

    // ---- gate-based CTA skip (exact: update kernel ignores out when s==0) ----
    if (S) {
        const int b0 = n0 >> 2;   // C_=4
        bool act = false;
        #pragma unroll
        for (int i = 0; i < 16; i++) act |= (S[b0 + i] != 0.0f);
        if (!act) return;         // uniform across block, before any __syncthreads
    }

    // ---- load X tile transposed: Xs[k][t] ----
    {
        #pragma unroll
        for (int r = 0; r < 16; r++) {
            int idx = tid + r * 256;          // 0..4095 = 64 t * 64 float4
            int t   = idx >> 6;
            int k4  = idx & 63;
            float4 v = *(const float4*)(X + (size_t)(n0 + t) * D_ + k4 * 4);
            int k = k4 * 4;
            Xs[(k + 0) * 68 + t] = v.x;
            Xs[(k + 1) * 68 + t] = v.y;
            Xs[(k + 2) * 68 + t] = v.z;
            Xs[(k + 3) * 68 + t] = v.w;
        }
        // load Wg (256x8) into Ws
        for (int i = tid; i < (D_ * E_) / 4; i += NTHREADS_)
            ((float4*)Ws)[i] = ((const float4*)Wg)[i];
    }
    __syncthreads();

    // ---- gating logits: 64 tokens x 8 experts ----
    for (int p = tid; p < TM_ * E_; p += NTHREADS_) {
        int t = p >> 3, e = p & 7;
        float acc = bg[e];
        for (int k = 0; k < D_; k++)
            acc += Xs[k * 68 + t] * Ws[k * 8 + e];
        LG[t * 8 + e] = acc;
    }
    __syncthreads();
    if (tid < TM_) {
        float m = -1e30f;
        #pragma unroll
        for (int e = 0; e < 8; e++) m = fmaxf(m, LG[tid * 8 + e]);
        float ex[8], ssum = 0.0f;
        #pragma unroll
        for (int e = 0; e < 8; e++) { ex[e] = expf(LG[tid * 8 + e] - m); ssum += ex[e]; }
        float inv = 1.0f / ssum;
        #pragma unroll
        for (int e = 0; e < 8; e++) LG[tid * 8 + e] = ex[e] * inv;
    }
    // (sync before experts overwrite Ws handled by first sync in kc loop)

    // output accumulator: 8 tokens x 4 out-cols per thread
    float outacc[8][4];
    #pragma unroll
    for (int i = 0; i < 8; i++)
        #pragma unroll
        for (int j = 0; j < 4; j++) outacc[i][j] = 0.0f;

    const int tbase = wid << 3;   // this thread's first token (0..56)

    for (int e = 0; e < E_; e++) {
        // ================= Phase A: h = relu(X @ We1[e] + be1[e]) =============
        const float* W1 = We1 + (size_t)e * D_ * H_;
        float acc[8][8];
        #pragma unroll
        for (int i = 0; i < 8; i++)
            #pragma unroll
            for (int j = 0; j < 8; j++) acc[i][j] = 0.0f;

        for (int kc = 0; kc < 4; kc++) {
            __syncthreads();   // protect Ws reuse (gating / prev expert / prev chunk)
            {
                const float4* src = (const float4*)(W1 + kc * 64 * H_);
                float4* dst = (float4*)Ws;
                #pragma unroll
                for (int r = 0; r < 16; r++) dst[tid + r * 256] = src[tid + r * 256];
            }
            __syncthreads();
            #pragma unroll 2
            for (int k = 0; k < 64; k++) {
                const float* xr = &Xs[(kc * 64 + k) * 68 + tbase];
                float4 x0 = *(const float4*)xr;
                float4 x1 = *(const float4*)(xr + 4);
                const float* wr = &Ws[k * 256 + lane];
                #pragma unroll
                for (int j = 0; j < 8; j++) {
                    float w = wr[j * 32];
                    acc[0][j] += x0.x * w;  acc[1][j] += x0.y * w;
                    acc[2][j] += x0.z * w;  acc[3][j] += x0.w * w;
                    acc[4][j] += x1.x * w;  acc[5][j] += x1.y * w;
                    acc[6][j] += x1.z * w;  acc[7][j] += x1.w * w;
                }
            }
        }
        // bias + relu -> Hs[h][t]
        #pragma unroll
        for (int j = 0; j < 8; j++) {
            int hc = j * 32 + lane;
            float b1 = be1[e * H_ + hc];
            float4 v0, v1;
            v0.x = fmaxf(acc[0][j] + b1, 0.0f); v0.y = fmaxf(acc[1][j] + b1, 0.0f);
            v0.z = fmaxf(acc[2][j] + b1, 0.0f); v0.w = fmaxf(acc[3][j] + b1, 0.0f);
            v1.x = fmaxf(acc[4][j] + b1, 0.0f); v1.y = fmaxf(acc[5][j] + b1, 0.0f);
            v1.z = fmaxf(acc[6][j] + b1, 0.0f); v1.w = fmaxf(acc[7][j] + b1, 0.0f);
            *(float4*)&Hs[hc * 68 + tbase]     = v0;
            *(float4*)&Hs[hc * 68 + tbase + 4] = v1;
        }
        __syncthreads();

        // ================= Phase B: eo = h @ We2[e] ===========================
        const float* W2 = We2 + (size_t)e * H_ * O_;
        float acc2[8][4];
        #pragma unroll
        for (int i = 0; i < 8; i++)
            #pragma unroll
            for (int j = 0; j < 4; j++) acc2[i][j] = 0.0f;

        for (int kc = 0; kc < 2; kc++) {
            __syncthreads();
            {
                const float4* src = (const float4*)(W2 + kc * 128 * O_);
                float4* dst = (float4*)Ws;
                #pragma unroll
                for (int r = 0; r < 16; r++) dst[tid + r * 256] = src[tid + r * 256];
            }
            __syncthreads();
            #pragma unroll 2
            for (int k = 0; k < 128; k++) {
                const float* hr = &Hs[(kc * 128 + k) * 68 + tbase];
                float4 h0 = *(const float4*)hr;
                float4 h1 = *(const float4*)(hr + 4);
                const float* wr = &Ws[k * 128 + lane];
                #pragma unroll
                for (int j = 0; j < 4; j++) {
                    float w = wr[j * 32];
                    acc2[0][j] += h0.x * w;  acc2[1][j] += h0.y * w;
                    acc2[2][j] += h0.z * w;  acc2[3][j] += h0.w * w;
                    acc2[4][j] += h1.x * w;  acc2[5][j] += h1.y * w;
                    acc2[6][j] += h1.z * w;  acc2[7][j] += h1.w * w;
                }
            }
        }
        // weight by gate + be2
        float b2[4];
        #pragma unroll
        for (int j = 0; j < 4; j++) b2[j] = be2[e * O_ + j * 32 + lane];
        #pragma unroll
        for (int i = 0; i < 8; i++) {
            float gi = LG[(tbase + i) * 8 + e];
            #pragma unroll
            for (int j = 0; j < 4; j++)
                outacc[i][j] += gi * (acc2[i][j] + b2[j]);
        }
    }

    // ---- write out (N x 128) ----
    #pragma unroll
    for (int i = 0; i < 8; i++) {
        float* row = Out + (size_t)(n0 + tbase + i) * O_ + lane;
        #pragma unroll
        for (int j = 0; j < 4; j++) row[j * 32] = outacc[i][j];
    }
}

// ---------------------------------------------------------------------------
// Generic tiled SGEMM: C[n, m0:m0+256] = (relu?)(A[N x K] @ W[K x M] + bias)
// grid.x = N/64, grid.y = M/256; K multiple of 64.
// smem: As[64][68] + Ws[64*256] = 20736 floats = 82944 B
// ---------------------------------------------------------------------------
#define GEMM_SMEM_BYTES ((64*68 + 64*256) * 4)

template<bool RELU>
__global__ void __launch_bounds__(NTHREADS_, 2)
gemm_tile_kernel(const float* __restrict__ A, const float* __restrict__ W,
                 const float* __restrict__ bias, float* __restrict__ Cout,
                 int K, int M, const float* __restrict__ S)
{
    extern __shared__ float sm[];
    float* As = sm;            // [64][68]
    float* Ws = sm + 64 * 68;  // [64][256]

    const int tid  = threadIdx.x;
    const int lane = tid & 31;
    const int wid  = tid >> 5;
    const int n0   = blockIdx.x * TM_;
    const int m0   = blockIdx.y * 256;

    if (S) {
        const int b0 = n0 >> 2;
        bool act = false;
        #pragma unroll
        for (int i = 0; i < 16; i++) act |= (S[b0 + i] != 0.0f);
        if (!act) return;
    }

    float acc[8][8];
    #pragma unroll
    for (int i = 0; i < 8; i++)
        #pragma unroll
        for (int j = 0; j < 8; j++) acc[i][j] = 0.0f;

    const int tbase = wid << 3;
    const int nchunks = K >> 6;

    for (int kc = 0; kc < nchunks; kc++) {
        __syncthreads();
        // A chunk transposed: As[k][t]
        #pragma unroll
        for (int r = 0; r < 4; r++) {
            int idx = tid + r * 256;       // 0..1023 = 64 t * 16 float4
            int t = idx >> 4, k4 = idx & 15;
            float4 v = *(const float4*)(A + (size_t)(n0 + t) * K + kc * 64 + k4 * 4);
            int k = k4 * 4;
            As[(k + 0) * 68 + t] = v.x;
            As[(k + 1) * 68 + t] = v.y;
            As[(k + 2) * 68 + t] = v.z;
            As[(k + 3) * 68 + t] = v.w;
        }
        // W chunk: Ws[k][c] (row-major slab)
        #pragma unroll
        for (int r = 0; r < 16; r++) {
            int idx = tid + r * 256;       // 0..4095 = 64 k * 64 float4
            int k = idx >> 6, c4 = idx & 63;
            *(float4*)&Ws[k * 256 + c4 * 4] =
                *(const float4*)(W + (size_t)(kc * 64 + k) * M + m0 + c4 * 4);
        }
        __syncthreads();
        #pragma unroll 2
        for (int k = 0; k < 64; k++) {
            const float* xr = &As[k * 68 + tbase];
            float4 x0 = *(const float4*)xr;
            float4 x1 = *(const float4*)(xr + 4);
            const float* wr = &Ws[k * 256 + lane];
            #pragma unroll
            for (int j = 0; j < 8; j++) {
                float w = wr[j * 32];
                acc[0][j] += x0.x * w;  acc[1][j] += x0.y * w;
                acc[2][j] += x0.z * w;  acc[3][j] += x0.w * w;
                acc[4][j] += x1.x * w;  acc[5][j] += x1.y * w;
                acc[6][j] += x1.z * w;  acc[7][j] += x1.w * w;
            }
        }
    }

    #pragma unroll
    for (int j = 0; j < 8; j++) {
        int col = m0 + j * 32 + lane;
        float bv = bias[col];
        #pragma unroll
        for (int i = 0; i < 8; i++) {
            float v = acc[i][j] + bv;
            if (RELU) v = fmaxf(v, 0.0f);
            Cout[(size_t)(n0 + tbase + i) * M + col] = v;
        }
    }
}

// ---------------------------------------------------------------------------
// Gate / update: one warp per batch row.
//   if out && s!=0:  result[b] += out[b] * s
//   co = softmax2(result[b] @ Wog + bog); S[b] = co0 > thresh ? co0 : 0
// ---------------------------------------------------------------------------
__global__ void __launch_bounds__(NTHREADS_)
gate_update_kernel(float* __restrict__ result, const float* __restrict__ out,
                   float* __restrict__ S, const float* __restrict__ Wog,
                   const float* __restrict__ bog, float thresh)
{
    const int lane = threadIdx.x & 31;
    const int wid  = threadIdx.x >> 5;
    const int b    = blockIdx.x * 8 + wid;

    float s = 0.0f;
    if (out) s = S[b];
    const bool do_add = (out != nullptr) && (s != 0.0f);

    float* row = result + (size_t)b * CO_;
    const float* orow = do_add ? (out + (size_t)b * CO_) : nullptr;

    float l0 = 0.0f, l1 = 0.0f;
    for (int k = lane * 4; k < CO_; k += 128) {
        float4 r = *(const float4*)&row[k];
        if (do_add) {
            float4 o = *(const float4*)&orow[k];
            r.x += o.x * s; r.y += o.y * s; r.z += o.z * s; r.w += o.w * s;
            *(float4*)&row[k] = r;
        }
        float4 wA = *(const float4*)&Wog[2 * k];       // rows k, k+1
        float4 wB = *(const float4*)&Wog[2 * k + 4];   // rows k+2, k+3
        l0 += r.x * wA.x + r.y * wA.z + r.z * wB.x + r.w * wB.z;
        l1 += r.x * wA.y + r.y * wA.w + r.z * wB.y + r.w * wB.w;
    }
    #pragma unroll
    for (int off = 16; off; off >>= 1) {
        l0 += __shfl_xor_sync(0xffffffffu, l0, off);
        l1 += __shfl_xor_sync(0xffffffffu, l1, off);
    }
    if (lane == 0) {
        l0 += bog[0]; l1 += bog[1];
        float m  = fmaxf(l0, l1);
        float e0 = expf(l0 - m), e1 = expf(l1 - m);
        float co0 = e0 / (e0 + e1);
        S[b] = (co0 > thresh) ? co0 : 0.0f;
    }
}

// ---------------------------------------------------------------------------
// Q head tail: values[b] = hq[b] @ Wq2 + bq2   (512 -> 18), one warp per row
// ---------------------------------------------------------------------------
__global__ void __launch_bounds__(NTHREADS_)
qhead_kernel(const float* __restrict__ hq, const float* __restrict__ Wq2,
             const float* __restrict__ bq2, float* __restrict__ outv)
{
    __shared__ float W2s[HQ_ * AQ_];   // 36864 B
    const int tid = threadIdx.x;
    for (int i = tid; i < HQ_ * AQ_; i += NTHREADS_) W2s[i] = Wq2[i];
    __syncthreads();

    const int lane = tid & 31;
    const int wid  = tid >> 5;
    const int b    = blockIdx.x * 8 + wid;

    const float* row = hq + (size_t)b * HQ_;
    float acc[AQ_];
    #pragma unroll
    for (int a = 0; a < AQ_; a++) acc[a] = 0.0f;
    for (int k = lane; k < HQ_; k += 32) {
        float v = row[k];
        const float* wr = &W2s[k * AQ_];
        #pragma unroll
        for (int a = 0; a < AQ_; a++) acc[a] += v * wr[a];
    }
    #pragma unroll
    for (int a = 0; a < AQ_; a++)
        #pragma unroll
        for (int off = 16; off; off >>= 1)
            acc[a] += __shfl_xor_sync(0xffffffffu, acc[a], off);
    if (lane == 0) {
        #pragma unroll
        for (int a = 0; a < AQ_; a++) outv[(size_t)b * AQ_ + a] = acc[a] + bq2[a];
    }
}

// ---------------------------------------------------------------------------
// Launch
// ---------------------------------------------------------------------------
extern "C" void kernel_launch(void* const* d_in, const int* in_sizes, int n_in,
                              void* d_out, int out_size)
{
    const float* data = (const float*)d_in[0];
    const float* We1  = (const float*)d_in[1];
    const float* be1  = (const float*)d_in[2];
    const float* We2  = (const float*)d_in[3];
    const float* be2  = (const float*)d_in[4];
    const float* Wg   = (const float*)d_in[5];
    const float* bg   = (const float*)d_in[6];
    const float* Wog  = (const float*)d_in[7];
    const float* bog  = (const float*)d_in[8];
    const float* Wr   = (const float*)d_in[9];
    const float* br   = (const float*)d_in[10];
    const float* Wq1  = (const float*)d_in[11];
    const float* bq1  = (const float*)d_in[12];
    const float* Wq2  = (const float*)d_in[13];
    const float* bq2  = (const float*)d_in[14];
    float* outp = (float*)d_out;

    cudaFuncSetAttribute(moe_kernel, cudaFuncAttributeMaxDynamicSharedMemorySize, MOE_SMEM_BYTES);
    cudaFuncSetAttribute(gemm_tile_kernel<false>, cudaFuncAttributeMaxDynamicSharedMemorySize, GEMM_SMEM_BYTES);
    cudaFuncSetAttribute(gemm_tile_kernel<true>,  cudaFuncAttributeMaxDynamicSharedMemorySize, GEMM_SMEM_BYTES);

    float *res_p, *out_p, *x2_p, *hq_p, *s_p;
    cudaGetSymbolAddress((void**)&res_p, g_result);
    cudaGetSymbolAddress((void**)&out_p, g_out);
    cudaGetSymbolAddress((void**)&x2_p,  g_x2);
    cudaGetSymbolAddress((void**)&hq_p,  g_hq);
    cudaGetSymbolAddress((void**)&s_p,   g_s);

    const dim3 moe_grid(N_ / TM_);            // 512
    const dim3 rmap_grid(N_ / TM_, 1);        // 512 x 1   (K=128, M=256)
    const dim3 hq_grid(B_ / TM_, HQ_ / 256);  // 128 x 2   (K=512, M=512)
    const dim3 row_grid(B_ / 8);              // 1024

    // 1) initial MoE forward: result = moe(data)
    moe_kernel<<<moe_grid, NTHREADS_, MOE_SMEM_BYTES>>>(
        data, We1, be1, We2, be2, Wg, bg, res_p, nullptr);

    // 2) initial gate (thresh = 0.3)
    gate_update_kernel<<<row_grid, NTHREADS_>>>(res_p, nullptr, s_p, Wog, bog, 0.3f);

    // recursion, unrolled 2x
    for (int it = 0; it < 2; it++) {
        // r = result.view(N,128) @ Wr + br
        gemm_tile_kernel<false><<<rmap_grid, NTHREADS_, GEMM_SMEM_BYTES>>>(
            res_p, Wr, br, x2_p, O_, D_, s_p);
        // out = moe(r)
        moe_kernel<<<moe_grid, NTHREADS_, MOE_SMEM_BYTES>>>(
            x2_p, We1, be1, We2, be2, Wg, bg, out_p, s_p);
        // result += out * s ; recompute gate (thresh = 0.5)
        gate_update_kernel<<<row_grid, NTHREADS_>>>(res_p, out_p, s_p, Wog, bog, 0.5f);
    }

    // Q head: hq = relu(result @ Wq1 + bq1); values = hq @ Wq2 + bq2
    gemm_tile_kernel<true><<<hq_grid, NTHREADS_, GEMM_SMEM_BYTES>>>(
        res_p, Wq1, bq1, hq_p, HQ_, HQ_, nullptr);
    qhead_kernel<<<row_grid, NTHREADS_>>>(hq_p, Wq2, bq2, outp);

    (void)in_sizes; (void)n_in; (void)out_size;
}

// round 2
// speedup vs baseline: 1.0010x; 1.0010x over previous
#include <cuda_runtime.h>
#include <math.h>

// ---------------------------------------------------------------------------
// MixtureOfExperts_33844342292483 — fp32 baseline (round 0)
// B=8192, C=4, D=256, E=8, H=256, O=128, CO=512, HQ=512, AQ=18
// ---------------------------------------------------------------------------

#define B_   8192
#define C_   4
#define D_   256
#define E_   8
#define H_   256
#define O_   128
#define CO_  512
#define HQ_  512
#define AQ_  18
#define N_   (B_ * C_)            // 32768 tokens

#define TM_  64                   // tokens per CTA
#define NTHREADS_ 256

// Scratch (device globals — no allocation allowed)
__device__ float g_result[B_ * CO_];   // 16 MB
__device__ float g_out   [B_ * CO_];   // 16 MB
__device__ float g_x2    [N_ * D_];    // 32 MB
__device__ float g_hq    [B_ * HQ_];   // 16 MB
__device__ float g_s     [B_];         // gate scale per batch row

// ---------------------------------------------------------------------------
// Fused MoE forward: Out[n, 0:128] = sum_e g[n,e] * (relu(X@We1[e]+be1[e]) @ We2[e] + be2[e])
// X: N x 256. Grid: N/64 CTAs, 256 threads.
// smem: Xs[256][68] + Hs[256][68] + Ws[16384] + LG[64*8] = 51712 floats = 206848 B
// ---------------------------------------------------------------------------
#define MOE_SMEM_FLOATS (256*68 + 256*68 + 16384 + 512)
#define MOE_SMEM_BYTES  (MOE_SMEM_FLOATS * 4)

__global__ void __launch_bounds__(NTHREADS_, 1)
moe_kernel(const float* __restrict__ X,
           const float* __restrict__ We1, const float* __restrict__ be1,
           const float* __restrict__ We2, const float* __restrict__ be2,
           const float* __restrict__ Wg,  const float* __restrict__ bg,
           float* __restrict__ Out,
           const float* __restrict__ S)   // per-batch gate scale, or null (all active)
{
    extern __shared__ float sm[];
    float* Xs = sm;                    // [k=256][t=68 pad]
    float* Hs = sm + 256 * 68;         // [h=256][t=68 pad]
    float* Ws = sm + 2 * 256 * 68;     // 16384 floats (weight chunks / Wg)
    float* LG = Ws + 16384;            // [64][8] gating logits -> softmax

    const int tid  = threadIdx.x;
    const int lane = tid & 31;
    const int wid  = tid >> 5;
    const int n0   = blockIdx.x * TM_;

    // ---- gate-based CTA skip (exact: update kernel ignores out when s==0) ----
    if (S) {
        const int b0 = n0 >> 2;   // C_=4
        bool act = false;
        #pragma unroll
        for (int i = 0; i < 16; i++) act |= (S[b0 + i] != 0.0f);
        if (!act) return;         // uniform across block, before any __syncthreads
    }

    // ---- load X tile transposed: Xs[k][t] ----
    {
        #pragma unroll
        for (int r = 0; r < 16; r++) {
            int idx = tid + r * 256;          // 0..4095 = 64 t * 64 float4
            int t   = idx >> 6;
            int k4  = idx & 63;
            float4 v = *(const float4*)(X + (size_t)(n0 + t) * D_ + k4 * 4);
            int k = k4 * 4;
            Xs[(k + 0) * 68 + t] = v.x;
            Xs[(k + 1) * 68 + t] = v.y;
            Xs[(k + 2) * 68 + t] = v.z;
            Xs[(k + 3) * 68 + t] = v.w;
        }
        // load Wg (256x8) into Ws
        for (int i = tid; i < (D_ * E_) / 4; i += NTHREADS_)
            ((float4*)Ws)[i] = ((const float4*)Wg)[i];
    }
    __syncthreads();

    // ---- gating logits: 64 tokens x 8 experts ----
    for (int p = tid; p < TM_ * E_; p += NTHREADS_) {
        int t = p >> 3, e = p & 7;
        float acc = bg[e];
        for (int k = 0; k < D_; k++)
            acc += Xs[k * 68 + t] * Ws[k * 8 + e];
        LG[t * 8 + e] = acc;
    }
    __syncthreads();
    if (tid < TM_) {
        float m = -1e30f;
        #pragma unroll
        for (int e = 0; e < 8; e++) m = fmaxf(m, LG[tid * 8 + e]);
        float ex[8], ssum = 0.0f;
        #pragma unroll
        for (int e = 0; e < 8; e++) { ex[e] = expf(LG[tid * 8 + e] - m); ssum += ex[e]; }
        float inv = 1.0f / ssum;
        #pragma unroll
        for (int e = 0; e < 8; e++) LG[tid * 8 + e] = ex[e] * inv;
    }
    // (sync before experts overwrite Ws handled by first sync in kc loop)

    // output accumulator: 8 tokens x 4 out-cols per thread
    float outacc[8][4];
    #pragma unroll
    for (int i = 0; i < 8; i++)
        #pragma unroll
        for (int j = 0; j < 4; j++) outacc[i][j] = 0.0f;

    const int tbase = wid << 3;   // this thread's first token (0..56)

    for (int e = 0; e < E_; e++) {
        // ================= Phase A: h = relu(X @ We1[e] + be1[e]) =============
        const float* W1 = We1 + (size_t)e * D_ * H_;
        float acc[8][8];
        #pragma unroll
        for (int i = 0; i < 8; i++)
            #pragma unroll
            for (int j = 0; j < 8; j++) acc[i][j] = 0.0f;

        for (int kc = 0; kc < 4; kc++) {
            __syncthreads();   // protect Ws reuse (gating / prev expert / prev chunk)
            {
                const float4* src = (const float4*)(W1 + kc * 64 * H_);
                float4* dst = (float4*)Ws;
                #pragma unroll
                for (int r = 0; r < 16; r++) dst[tid + r * 256] = src[tid + r * 256];
            }
            __syncthreads();
            #pragma unroll 2
            for (int k = 0; k < 64; k++) {
                const float* xr = &Xs[(kc * 64 + k) * 68 + tbase];
                float4 x0 = *(const float4*)xr;
                float4 x1 = *(const float4*)(xr + 4);
                const float* wr = &Ws[k * 256 + lane];
                #pragma unroll
                for (int j = 0; j < 8; j++) {
                    float w = wr[j * 32];
                    acc[0][j] += x0.x * w;  acc[1][j] += x0.y * w;
                    acc[2][j] += x0.z * w;  acc[3][j] += x0.w * w;
                    acc[4][j] += x1.x * w;  acc[5][j] += x1.y * w;
                    acc[6][j] += x1.z * w;  acc[7][j] += x1.w * w;
                }
            }
        }
        // bias + relu -> Hs[h][t]
        #pragma unroll
        for (int j = 0; j < 8; j++) {
            int hc = j * 32 + lane;
            float b1 = be1[e * H_ + hc];
            float4 v0, v1;
            v0.x = fmaxf(acc[0][j] + b1, 0.0f); v0.y = fmaxf(acc[1][j] + b1, 0.0f);
            v0.z = fmaxf(acc[2][j] + b1, 0.0f); v0.w = fmaxf(acc[3][j] + b1, 0.0f);
            v1.x = fmaxf(acc[4][j] + b1, 0.0f); v1.y = fmaxf(acc[5][j] + b1, 0.0f);
            v1.z = fmaxf(acc[6][j] + b1, 0.0f); v1.w = fmaxf(acc[7][j] + b1, 0.0f);
            *(float4*)&Hs[hc * 68 + tbase]     = v0;
            *(float4*)&Hs[hc * 68 + tbase + 4] = v1;
        }
        __syncthreads();

        // ================= Phase B: eo = h @ We2[e] ===========================
        const float* W2 = We2 + (size_t)e * H_ * O_;
        float acc2[8][4];
        #pragma unroll
        for (int i = 0; i < 8; i++)
            #pragma unroll
            for (int j = 0; j < 4; j++) acc2[i][j] = 0.0f;

        for (int kc = 0; kc < 2; kc++) {
            __syncthreads();
            {
                const float4* src = (const float4*)(W2 + kc * 128 * O_);
                float4* dst = (float4*)Ws;
                #pragma unroll
                for (int r = 0; r < 16; r++) dst[tid + r * 256] = src[tid + r * 256];
            }
            __syncthreads();
            #pragma unroll 2
            for (int k = 0; k < 128; k++) {
                const float* hr = &Hs[(kc * 128 + k) * 68 + tbase];
                float4 h0 = *(const float4*)hr;
                float4 h1 = *(const float4*)(hr + 4);
                const float* wr = &Ws[k * 128 + lane];
                #pragma unroll
                for (int j = 0; j < 4; j++) {
                    float w = wr[j * 32];
                    acc2[0][j] += h0.x * w;  acc2[1][j] += h0.y * w;
                    acc2[2][j] += h0.z * w;  acc2[3][j] += h0.w * w;
                    acc2[4][j] += h1.x * w;  acc2[5][j] += h1.y * w;
                    acc2[6][j] += h1.z * w;  acc2[7][j] += h1.w * w;
                }
            }
        }
        // weight by gate + be2
        float b2[4];
        #pragma unroll
        for (int j = 0; j < 4; j++) b2[j] = be2[e * O_ + j * 32 + lane];
        #pragma unroll
        for (int i = 0; i < 8; i++) {
            float gi = LG[(tbase + i) * 8 + e];
            #pragma unroll
            for (int j = 0; j < 4; j++)
                outacc[i][j] += gi * (acc2[i][j] + b2[j]);
        }
    }

    // ---- write out (N x 128) ----
    #pragma unroll
    for (int i = 0; i < 8; i++) {
        float* row = Out + (size_t)(n0 + tbase + i) * O_ + lane;
        #pragma unroll
        for (int j = 0; j < 4; j++) row[j * 32] = outacc[i][j];
    }
}

// ---------------------------------------------------------------------------
// Generic tiled SGEMM: C[n, m0:m0+256] = (relu?)(A[N x K] @ W[K x M] + bias)
// grid.x = N/64, grid.y = M/256; K multiple of 64.
// smem: As[64][68] + Ws[64*256] = 20736 floats = 82944 B
// ---------------------------------------------------------------------------
#define GEMM_SMEM_BYTES ((64*68 + 64*256) * 4)

template<bool RELU>
__global__ void __launch_bounds__(NTHREADS_, 2)
gemm_tile_kernel(const float* __restrict__ A, const float* __restrict__ W,
                 const float* __restrict__ bias, float* __restrict__ Cout,
                 int K, int M, const float* __restrict__ S)
{
    extern __shared__ float sm[];
    float* As = sm;            // [64][68]
    float* Ws = sm + 64 * 68;  // [64][256]

    const int tid  = threadIdx.x;
    const int lane = tid & 31;
    const int wid  = tid >> 5;
    const int n0   = blockIdx.x * TM_;
    const int m0   = blockIdx.y * 256;

    if (S) {
        const int b0 = n0 >> 2;
        bool act = false;
        #pragma unroll
        for (int i = 0; i < 16; i++) act |= (S[b0 + i] != 0.0f);
        if (!act) return;
    }

    float acc[8][8];
    #pragma unroll
    for (int i = 0; i < 8; i++)
        #pragma unroll
        for (int j = 0; j < 8; j++) acc[i][j] = 0.0f;

    const int tbase = wid << 3;
    const int nchunks = K >> 6;

    for (int kc = 0; kc < nchunks; kc++) {
        __syncthreads();
        // A chunk transposed: As[k][t]
        #pragma unroll
        for (int r = 0; r < 4; r++) {
            int idx = tid + r * 256;       // 0..1023 = 64 t * 16 float4
            int t = idx >> 4, k4 = idx & 15;
            float4 v = *(const float4*)(A + (size_t)(n0 + t) * K + kc * 64 + k4 * 4);
            int k = k4 * 4;
            As[(k + 0) * 68 + t] = v.x;
            As[(k + 1) * 68 + t] = v.y;
            As[(k + 2) * 68 + t] = v.z;
            As[(k + 3) * 68 + t] = v.w;
        }
        // W chunk: Ws[k][c] (row-major slab)
        #pragma unroll
        for (int r = 0; r < 16; r++) {
            int idx = tid + r * 256;       // 0..4095 = 64 k * 64 float4
            int k = idx >> 6, c4 = idx & 63;
            *(float4*)&Ws[k * 256 + c4 * 4] =
                *(const float4*)(W + (size_t)(kc * 64 + k) * M + m0 + c4 * 4);
        }
        __syncthreads();
        #pragma unroll 2
        for (int k = 0; k < 64; k++) {
            const float* xr = &As[k * 68 + tbase];
            float4 x0 = *(const float4*)xr;
            float4 x1 = *(const float4*)(xr + 4);
            const float* wr = &Ws[k * 256 + lane];
            #pragma unroll
            for (int j = 0; j < 8; j++) {
                float w = wr[j * 32];
                acc[0][j] += x0.x * w;  acc[1][j] += x0.y * w;
                acc[2][j] += x0.z * w;  acc[3][j] += x0.w * w;
                acc[4][j] += x1.x * w;  acc[5][j] += x1.y * w;
                acc[6][j] += x1.z * w;  acc[7][j] += x1.w * w;
            }
        }
    }

    #pragma unroll
    for (int j = 0; j < 8; j++) {
        int col = m0 + j * 32 + lane;
        float bv = bias[col];
        #pragma unroll
        for (int i = 0; i < 8; i++) {
            float v = acc[i][j] + bv;
            if (RELU) v = fmaxf(v, 0.0f);
            Cout[(size_t)(n0 + tbase + i) * M + col] = v;
        }
    }
}

// ---------------------------------------------------------------------------
// Gate / update: one warp per batch row.
//   if out && s!=0:  result[b] += out[b] * s
//   co = softmax2(result[b] @ Wog + bog); S[b] = co0 > thresh ? co0 : 0
// ---------------------------------------------------------------------------
__global__ void __launch_bounds__(NTHREADS_)
gate_update_kernel(float* __restrict__ result, const float* __restrict__ out,
                   float* __restrict__ S, const float* __restrict__ Wog,
                   const float* __restrict__ bog, float thresh)
{
    const int lane = threadIdx.x & 31;
    const int wid  = threadIdx.x >> 5;
    const int b    = blockIdx.x * 8 + wid;

    float s = 0.0f;
    if (out) s = S[b];
    const bool do_add = (out != nullptr) && (s != 0.0f);

    float* row = result + (size_t)b * CO_;
    const float* orow = do_add ? (out + (size_t)b * CO_) : nullptr;

    float l0 = 0.0f, l1 = 0.0f;
    for (int k = lane * 4; k < CO_; k += 128) {
        float4 r = *(const float4*)&row[k];
        if (do_add) {
            float4 o = *(const float4*)&orow[k];
            r.x += o.x * s; r.y += o.y * s; r.z += o.z * s; r.w += o.w * s;
            *(float4*)&row[k] = r;
        }
        float4 wA = *(const float4*)&Wog[2 * k];       // rows k, k+1
        float4 wB = *(const float4*)&Wog[2 * k + 4];   // rows k+2, k+3
        l0 += r.x * wA.x + r.y * wA.z + r.z * wB.x + r.w * wB.z;
        l1 += r.x * wA.y + r.y * wA.w + r.z * wB.y + r.w * wB.w;
    }
    #pragma unroll
    for (int off = 16; off; off >>= 1) {
        l0 += __shfl_xor_sync(0xffffffffu, l0, off);
        l1 += __shfl_xor_sync(0xffffffffu, l1, off);
    }
    if (lane == 0) {
        l0 += bog[0]; l1 += bog[1];
        float m  = fmaxf(l0, l1);
        float e0 = expf(l0 - m), e1 = expf(l1 - m);
        float co0 = e0 / (e0 + e1);
        S[b] = (co0 > thresh) ? co0 : 0.0f;
    }
}

// ---------------------------------------------------------------------------
// Q head tail: values[b] = hq[b] @ Wq2 + bq2   (512 -> 18), one warp per row
// ---------------------------------------------------------------------------
__global__ void __launch_bounds__(NTHREADS_)
qhead_kernel(const float* __restrict__ hq, const float* __restrict__ Wq2,
             const float* __restrict__ bq2, float* __restrict__ outv)
{
    __shared__ float W2s[HQ_ * AQ_];   // 36864 B
    const int tid = threadIdx.x;
    for (int i = tid; i < HQ_ * AQ_; i += NTHREADS_) W2s[i] = Wq2[i];
    __syncthreads();

    const int lane = tid & 31;
    const int wid  = tid >> 5;
    const int b    = blockIdx.x * 8 + wid;

    const float* row = hq + (size_t)b * HQ_;
    float acc[AQ_];
    #pragma unroll
    for (int a = 0; a < AQ_; a++) acc[a] = 0.0f;
    for (int k = lane; k < HQ_; k += 32) {
        float v = row[k];
        const float* wr = &W2s[k * AQ_];
        #pragma unroll
        for (int a = 0; a < AQ_; a++) acc[a] += v * wr[a];
    }
    #pragma unroll
    for (int a = 0; a < AQ_; a++)
        #pragma unroll
        for (int off = 16; off; off >>= 1)
            acc[a] += __shfl_xor_sync(0xffffffffu, acc[a], off);
    if (lane == 0) {
        #pragma unroll
        for (int a = 0; a < AQ_; a++) outv[(size_t)b * AQ_ + a] = acc[a] + bq2[a];
    }
}

// ---------------------------------------------------------------------------
// Launch
// ---------------------------------------------------------------------------
extern "C" void kernel_launch(void* const* d_in, const int* in_sizes, int n_in,
                              void* d_out, int out_size)
{
    const float* data = (const float*)d_in[0];
    const float* We1  = (const float*)d_in[1];
    const float* be1  = (const float*)d_in[2];
    const float* We2  = (const float*)d_in[3];
    const float* be2  = (const float*)d_in[4];
    const float* Wg   = (const float*)d_in[5];
    const float* bg   = (const float*)d_in[6];
    const float* Wog  = (const float*)d_in[7];
    const float* bog  = (const float*)d_in[8];
    const float* Wr   = (const float*)d_in[9];
    const float* br   = (const float*)d_in[10];
    const float* Wq1  = (const float*)d_in[11];
    const float* bq1  = (const float*)d_in[12];
    const float* Wq2  = (const float*)d_in[13];
    const float* bq2  = (const float*)d_in[14];
    float* outp = (float*)d_out;

    cudaFuncSetAttribute(moe_kernel, cudaFuncAttributeMaxDynamicSharedMemorySize, MOE_SMEM_BYTES);
    cudaFuncSetAttribute(gemm_tile_kernel<false>, cudaFuncAttributeMaxDynamicSharedMemorySize, GEMM_SMEM_BYTES);
    cudaFuncSetAttribute(gemm_tile_kernel<true>,  cudaFuncAttributeMaxDynamicSharedMemorySize, GEMM_SMEM_BYTES);

    float *res_p, *out_p, *x2_p, *hq_p, *s_p;
    cudaGetSymbolAddress((void**)&res_p, g_result);
    cudaGetSymbolAddress((void**)&out_p, g_out);
    cudaGetSymbolAddress((void**)&x2_p,  g_x2);
    cudaGetSymbolAddress((void**)&hq_p,  g_hq);
    cudaGetSymbolAddress((void**)&s_p,   g_s);

    const dim3 moe_grid(N_ / TM_);            // 512
    const dim3 rmap_grid(N_ / TM_, 1);        // 512 x 1   (K=128, M=256)
    const dim3 hq_grid(B_ / TM_, HQ_ / 256);  // 128 x 2   (K=512, M=512)
    const dim3 row_grid(B_ / 8);              // 1024

    // 1) initial MoE forward: result = moe(data)
    moe_kernel<<<moe_grid, NTHREADS_, MOE_SMEM_BYTES>>>(
        data, We1, be1, We2, be2, Wg, bg, res_p, nullptr);

    // 2) initial gate (thresh = 0.3)
    gate_update_kernel<<<row_grid, NTHREADS_>>>(res_p, nullptr, s_p, Wog, bog, 0.3f);

    // recursion, unrolled 2x
    for (int it = 0; it < 2; it++) {
        // r = result.view(N,128) @ Wr + br
        gemm_tile_kernel<false><<<rmap_grid, NTHREADS_, GEMM_SMEM_BYTES>>>(
            res_p, Wr, br, x2_p, O_, D_, s_p);
        // out = moe(r)
        moe_kernel<<<moe_grid, NTHREADS_, MOE_SMEM_BYTES>>>(
            x2_p, We1, be1, We2, be2, Wg, bg, out_p, s_p);
        // result += out * s ; recompute gate (thresh = 0.5)
        gate_update_kernel<<<row_grid, NTHREADS_>>>(res_p, out_p, s_p, Wog, bog, 0.5f);
    }

    // Q head: hq = relu(result @ Wq1 + bq1); values = hq @ Wq2 + bq2
    gemm_tile_kernel<true><<<hq_grid, NTHREADS_, GEMM_SMEM_BYTES>>>(
        res_p, Wq1, bq1, hq_p, HQ_, HQ_, nullptr);
    qhead_kernel<<<row_grid, NTHREADS_>>>(hq_p, Wq2, bq2, outp);

    (void)in_sizes; (void)n_in; (void)out_size;
}

// round 5
// speedup vs baseline: 1.3330x; 1.3316x over previous
#include <cuda_runtime.h>
#include <cuda_bf16.h>
#include <stdint.h>
#include <math.h>

#define B_   8192
#define C_   4
#define D_   256
#define E_   8
#define H_   256
#define O_   128
#define CO_  512
#define HQ_  512
#define AQ_  18
#define N_   (B_ * C_)
#define NT_  256

__device__ float g_result[B_ * CO_];
__device__ float g_out   [B_ * CO_];
__device__ float g_x2    [N_ * D_];
__device__ float g_hq    [B_ * HQ_];
__device__ float g_s     [B_];
__device__ __nv_bfloat16 g_xs [3 * N_ * D_];        // X split planes [p][n][d]
__device__ __nv_bfloat16 g_w1t[3 * E_ * H_ * D_];   // [p][e][h][d]
__device__ __nv_bfloat16 g_w2t[3 * E_ * O_ * H_];   // [p][e][o][h]

__device__ __forceinline__ uint32_t smem_u32(const void* p) {
    uint32_t a;
    asm("{ .reg .u64 t; cvta.to.shared.u64 t, %1; cvt.u32.u64 %0, t; }" : "=r"(a) : "l"(p));
    return a;
}
__device__ __forceinline__ void ldsm4(uint32_t* r, uint32_t a) {
    asm volatile("ldmatrix.sync.aligned.m8n8.x4.shared.b16 {%0,%1,%2,%3}, [%4];"
                 : "=r"(r[0]), "=r"(r[1]), "=r"(r[2]), "=r"(r[3]) : "r"(a));
}
__device__ __forceinline__ void ldsm2(uint32_t* r, uint32_t a) {
    asm volatile("ldmatrix.sync.aligned.m8n8.x2.shared.b16 {%0,%1}, [%2];"
                 : "=r"(r[0]), "=r"(r[1]) : "r"(a));
}
__device__ __forceinline__ void mma16816(float* c, const uint32_t* a, const uint32_t* b) {
    asm volatile("mma.sync.aligned.m16n8k16.row.col.f32.bf16.bf16.f32 "
                 "{%0,%1,%2,%3}, {%4,%5,%6,%7}, {%8,%9}, {%0,%1,%2,%3};"
                 : "+f"(c[0]), "+f"(c[1]), "+f"(c[2]), "+f"(c[3])
                 : "r"(a[0]), "r"(a[1]), "r"(a[2]), "r"(a[3]), "r"(b[0]), "r"(b[1]));
}
__device__ __forceinline__ void split3(float x, unsigned short& h, unsigned short& m, unsigned short& l) {
    __nv_bfloat16 b0 = __float2bfloat16(x);
    float r = x - __bfloat162float(b0);
    __nv_bfloat16 b1 = __float2bfloat16(r);
    r -= __bfloat162float(b1);
    __nv_bfloat16 b2 = __float2bfloat16(r);
    h = __bfloat16_as_ushort(b0); m = __bfloat16_as_ushort(b1); l = __bfloat16_as_ushort(b2);
}
__device__ __forceinline__ uint32_t pack2(unsigned short a, unsigned short b) {
    return (uint32_t)a | ((uint32_t)b << 16);
}

// ---------------- split kernels ----------------
__global__ void split_x_kernel(const float* __restrict__ src, __nv_bfloat16* __restrict__ dst) {
    size_t i4 = (size_t)blockIdx.x * 256 + threadIdx.x;
    float4 v = ((const float4*)src)[i4];
    float xv[4] = {v.x, v.y, v.z, v.w};
    unsigned short hb[4], mb[4], lb[4];
    #pragma unroll
    for (int j = 0; j < 4; j++) split3(xv[j], hb[j], mb[j], lb[j]);
    const size_t S = (size_t)N_ * D_ / 4;
    uint2 u;
    u.x = pack2(hb[0], hb[1]); u.y = pack2(hb[2], hb[3]); ((uint2*)dst)[i4] = u;
    u.x = pack2(mb[0], mb[1]); u.y = pack2(mb[2], mb[3]); ((uint2*)dst)[i4 + S] = u;
    u.x = pack2(lb[0], lb[1]); u.y = pack2(lb[2], lb[3]); ((uint2*)dst)[i4 + 2 * S] = u;
}
__global__ void split_w1_kernel(const float* __restrict__ We1) {
    int idx = blockIdx.x * 256 + threadIdx.x;             // [e][h][d]
    int e = idx >> 16, h = (idx >> 8) & 255, d = idx & 255;
    unsigned short hb, mb, lb;
    split3(We1[((e * D_) + d) * H_ + h], hb, mb, lb);
    const int S = E_ * H_ * D_;
    g_w1t[idx] = __ushort_as_bfloat16(hb);
    g_w1t[idx + S] = __ushort_as_bfloat16(mb);
    g_w1t[idx + 2 * S] = __ushort_as_bfloat16(lb);
}
__global__ void split_w2_kernel(const float* __restrict__ We2) {
    int idx = blockIdx.x * 256 + threadIdx.x;             // [e][o][h]
    int e = idx >> 15, o = (idx >> 8) & 127, h = idx & 255;
    unsigned short hb, mb, lb;
    split3(We2[((e * H_) + h) * O_ + o], hb, mb, lb);
    const int S = E_ * O_ * H_;
    g_w2t[idx] = __ushort_as_bfloat16(hb);
    g_w2t[idx + S] = __ushort_as_bfloat16(mb);
    g_w2t[idx + 2 * S] = __ushort_as_bfloat16(lb);
}

// ---------------- MoE mma.sync kernel ----------------
// 64 tokens/CTA, 8 warps (2x4 grid of m32xn32 warp tiles).
#define XPL 33792
#define HPL 17408
#define WPL 18432
#define XS_OFF 0
#define HB_OFF 101376
#define WB_OFF 153600
#define LG_OFF 208896
#define MOE_SMEM 210944

__global__ void __launch_bounds__(NT_, 1)
moe_mma_kernel(const float* __restrict__ Xf, const __nv_bfloat16* __restrict__ XS,
               const __nv_bfloat16* __restrict__ W1T, const __nv_bfloat16* __restrict__ W2T,
               const float* __restrict__ be1, const float* __restrict__ be2,
               const float* __restrict__ Wg,  const float* __restrict__ bg,
               float* __restrict__ Out, const float* __restrict__ S)
{
    extern __shared__ char sm[];
    const int tid = threadIdx.x, lane = tid & 31, wid = tid >> 5;
    const int n0 = blockIdx.x * 64;

    if (S) {
        const int b0 = n0 >> 2;
        bool act = false;
        #pragma unroll
        for (int i = 0; i < 16; i++) act |= (S[b0 + i] != 0.0f);
        if (!act) return;
    }

    const uint32_t sb = smem_u32(sm);
    float* LG = (float*)(sm + LG_OFF);
    const size_t XST = (size_t)N_ * D_;
    const size_t W1S = (size_t)E_ * H_ * D_, W2S = (size_t)E_ * O_ * H_;

    // load X planes into padded smem
    #pragma unroll
    for (int it = 0; it < 24; it++) {
        int idx = tid + it * 256;
        int p = idx >> 11, rem = idx & 2047;
        int row = rem >> 5, c8 = rem & 31;
        uint4 v = *(const uint4*)(XS + (size_t)p * XST + (size_t)(n0 + row) * D_ + c8 * 8);
        *(uint4*)(sm + XS_OFF + p * XPL + row * 528 + c8 * 16) = v;
    }
    // gating logits (fp32)
    {
        int t = tid >> 2, e0 = (tid & 3) * 2;
        float a0 = 0.f, a1 = 0.f;
        const float* xr = Xf + (size_t)(n0 + t) * D_;
        for (int k = 0; k < D_; k += 4) {
            float4 xv = *(const float4*)(xr + k);
            a0 += xv.x * Wg[(k + 0) * 8 + e0] + xv.y * Wg[(k + 1) * 8 + e0]
                + xv.z * Wg[(k + 2) * 8 + e0] + xv.w * Wg[(k + 3) * 8 + e0];
            a1 += xv.x * Wg[(k + 0) * 8 + e0 + 1] + xv.y * Wg[(k + 1) * 8 + e0 + 1]
                + xv.z * Wg[(k + 2) * 8 + e0 + 1] + xv.w * Wg[(k + 3) * 8 + e0 + 1];
        }
        LG[t * 8 + e0] = a0 + bg[e0];
        LG[t * 8 + e0 + 1] = a1 + bg[e0 + 1];
    }
    __syncthreads();
    if (tid < 64) {
        float m = -1e30f;
        #pragma unroll
        for (int e = 0; e < 8; e++) m = fmaxf(m, LG[tid * 8 + e]);
        float ex[8], ss = 0.f;
        #pragma unroll
        for (int e = 0; e < 8; e++) { ex[e] = expf(LG[tid * 8 + e] - m); ss += ex[e]; }
        float inv = 1.0f / ss;
        #pragma unroll
        for (int e = 0; e < 8; e++) LG[tid * 8 + e] = ex[e] * inv;
    }
    __syncthreads();

    const int mw = (wid >> 2) * 32, nw = (wid & 3) * 32;
    const int PA[6] = {0, 0, 1, 1, 0, 2};
    const int PB[6] = {0, 1, 0, 1, 2, 0};

    float D2[2][4][4];
    #pragma unroll
    for (int i = 0; i < 2; i++)
        #pragma unroll
        for (int j = 0; j < 4; j++)
            #pragma unroll
            for (int q = 0; q < 4; q++) D2[i][j][q] = 0.f;

    const uint32_t aoffX = XS_OFF + (mw + (lane & 15)) * 528 + ((lane >> 4) << 3) * 2;
    const uint32_t aoffH = HB_OFF + (mw + (lane & 15)) * 272 + ((lane >> 4) << 3) * 2;
    const uint32_t boffW = WB_OFF + (nw + (lane & 7)) * 144 + (((lane >> 3) & 1) << 3) * 2;

    for (int e = 0; e < E_; e++)
    for (int half = 0; half < 2; half++) {
        float C1[2][4][4];
        #pragma unroll
        for (int i = 0; i < 2; i++)
            #pragma unroll
            for (int j = 0; j < 4; j++)
                #pragma unroll
                for (int q = 0; q < 4; q++) C1[i][j][q] = 0.f;

        // ---- GEMM1: C1 = X @ W1[e][:, half*128 : +128] ----
        for (int kc = 0; kc < 4; kc++) {
            __syncthreads();
            #pragma unroll
            for (int it = 0; it < 12; it++) {
                int idx = tid + it * 256;
                int p = idx >> 10, rem = idx & 1023;
                int nn = rem >> 3, c8 = rem & 7;
                uint4 v = *(const uint4*)(W1T + (size_t)p * W1S +
                    (size_t)(e * H_ + half * 128 + nn) * D_ + kc * 64 + c8 * 8);
                *(uint4*)(sm + WB_OFF + p * WPL + nn * 144 + c8 * 16) = v;
            }
            __syncthreads();
            for (int ks = 0; ks < 4; ks++) {
                const int kg = kc * 64 + ks * 16;
                uint32_t A[2][3][4], Bf[4][3][2];
                #pragma unroll
                for (int i = 0; i < 2; i++)
                    #pragma unroll
                    for (int p = 0; p < 3; p++)
                        ldsm4(A[i][p], sb + aoffX + p * XPL + i * 16 * 528 + kg * 2);
                #pragma unroll
                for (int j = 0; j < 4; j++)
                    #pragma unroll
                    for (int p = 0; p < 3; p++)
                        ldsm2(Bf[j][p], sb + boffW + p * WPL + j * 8 * 144 + ks * 32);
                #pragma unroll
                for (int pr = 0; pr < 6; pr++)
                    #pragma unroll
                    for (int i = 0; i < 2; i++)
                        #pragma unroll
                        for (int j = 0; j < 4; j++)
                            mma16816(C1[i][j], A[i][PA[pr]], Bf[j][PB[pr]]);
            }
        }

        // ---- epilogue: hbuf = split3(g * relu(C1 + be1)) ----
        #pragma unroll
        for (int i = 0; i < 2; i++) {
            int r0 = mw + i * 16 + (lane >> 2);
            float ga = LG[r0 * 8 + e], gb = LG[(r0 + 8) * 8 + e];
            #pragma unroll
            for (int j = 0; j < 4; j++) {
                int col = nw + j * 8 + (lane & 3) * 2;   // local h col 0..127
                float b1a = be1[e * H_ + half * 128 + col];
                float b1b = be1[e * H_ + half * 128 + col + 1];
                float v0 = fmaxf(C1[i][j][0] + b1a, 0.f) * ga;
                float v1 = fmaxf(C1[i][j][1] + b1b, 0.f) * ga;
                float v2 = fmaxf(C1[i][j][2] + b1a, 0.f) * gb;
                float v3 = fmaxf(C1[i][j][3] + b1b, 0.f) * gb;
                unsigned short h0, m0, l0, h1, m1, l1;
                uint32_t base0 = HB_OFF + r0 * 272 + col * 2;
                uint32_t base1 = HB_OFF + (r0 + 8) * 272 + col * 2;
                split3(v0, h0, m0, l0); split3(v1, h1, m1, l1);
                *(uint32_t*)(sm + base0)           = pack2(h0, h1);
                *(uint32_t*)(sm + base0 + HPL)     = pack2(m0, m1);
                *(uint32_t*)(sm + base0 + 2 * HPL) = pack2(l0, l1);
                split3(v2, h0, m0, l0); split3(v3, h1, m1, l1);
                *(uint32_t*)(sm + base1)           = pack2(h0, h1);
                *(uint32_t*)(sm + base1 + HPL)     = pack2(m0, m1);
                *(uint32_t*)(sm + base1 + 2 * HPL) = pack2(l0, l1);
            }
        }

        // ---- GEMM2 partial: D2 += hbuf @ W2[e][half*128 : +128, :] ----
        for (int kc2 = 0; kc2 < 2; kc2++) {
            __syncthreads();
            #pragma unroll
            for (int it = 0; it < 12; it++) {
                int idx = tid + it * 256;
                int p = idx >> 10, rem = idx & 1023;
                int nn = rem >> 3, c8 = rem & 7;
                uint4 v = *(const uint4*)(W2T + (size_t)p * W2S +
                    (size_t)(e * O_ + nn) * H_ + half * 128 + kc2 * 64 + c8 * 8);
                *(uint4*)(sm + WB_OFF + p * WPL + nn * 144 + c8 * 16) = v;
            }
            __syncthreads();
            for (int ks = 0; ks < 4; ks++) {
                const int kl = kc2 * 64 + ks * 16;
                uint32_t A[2][3][4], Bf[4][3][2];
                #pragma unroll
                for (int i = 0; i < 2; i++)
                    #pragma unroll
                    for (int p = 0; p < 3; p++)
                        ldsm4(A[i][p], sb + aoffH + p * HPL + i * 16 * 272 + kl * 2);
                #pragma unroll
                for (int j = 0; j < 4; j++)
                    #pragma unroll
                    for (int p = 0; p < 3; p++)
                        ldsm2(Bf[j][p], sb + boffW + p * WPL + j * 8 * 144 + ks * 32);
                #pragma unroll
                for (int pr = 0; pr < 6; pr++)
                    #pragma unroll
                    for (int i = 0; i < 2; i++)
                        #pragma unroll
                        for (int j = 0; j < 4; j++)
                            mma16816(D2[i][j], A[i][PA[pr]], Bf[j][PB[pr]]);
            }
        }
    }

    // ---- final epilogue: Out = D2 + sum_e g_e * be2[e] ----
    #pragma unroll
    for (int i = 0; i < 2; i++) {
        int r0 = mw + i * 16 + (lane >> 2);
        float ga[8], gb[8];
        #pragma unroll
        for (int e = 0; e < 8; e++) { ga[e] = LG[r0 * 8 + e]; gb[e] = LG[(r0 + 8) * 8 + e]; }
        #pragma unroll
        for (int j = 0; j < 4; j++) {
            int col = nw + j * 8 + (lane & 3) * 2;
            float b0a = 0.f, b1a = 0.f, b0b = 0.f, b1b = 0.f;
            #pragma unroll
            for (int e = 0; e < 8; e++) {
                float w0 = be2[e * O_ + col], w1 = be2[e * O_ + col + 1];
                b0a += ga[e] * w0; b1a += ga[e] * w1;
                b0b += gb[e] * w0; b1b += gb[e] * w1;
            }
            *(float2*)(Out + (size_t)(n0 + r0) * O_ + col) =
                make_float2(D2[i][j][0] + b0a, D2[i][j][1] + b1a);
            *(float2*)(Out + (size_t)(n0 + r0 + 8) * O_ + col) =
                make_float2(D2[i][j][2] + b0b, D2[i][j][3] + b1b);
        }
    }
}

// ---------------- fp32 tail kernels ----------------
#define GEMM_SMEM ((64*68 + 64*256) * 4)
template<bool RELU>
__global__ void __launch_bounds__(NT_, 2)
gemm_tile_kernel(const float* __restrict__ A, const float* __restrict__ W,
                 const float* __restrict__ bias, float* __restrict__ Cout,
                 int K, int M, const float* __restrict__ S)
{
    extern __shared__ float smf[];
    float* As = smf;
    float* Ws = smf + 64 * 68;
    const int tid = threadIdx.x, lane = tid & 31, wid = tid >> 5;
    const int n0 = blockIdx.x * 64, m0 = blockIdx.y * 256;
    if (S) {
        const int b0 = n0 >> 2;
        bool act = false;
        #pragma unroll
        for (int i = 0; i < 16; i++) act |= (S[b0 + i] != 0.0f);
        if (!act) return;
    }
    float acc[8][8];
    #pragma unroll
    for (int i = 0; i < 8; i++)
        #pragma unroll
        for (int j = 0; j < 8; j++) acc[i][j] = 0.0f;
    const int tb = wid << 3;
    for (int kc = 0; kc < (K >> 6); kc++) {
        __syncthreads();
        #pragma unroll
        for (int r = 0; r < 4; r++) {
            int idx = tid + r * 256, t = idx >> 4, k4 = idx & 15;
            float4 v = *(const float4*)(A + (size_t)(n0 + t) * K + kc * 64 + k4 * 4);
            int k = k4 * 4;
            As[(k + 0) * 68 + t] = v.x; As[(k + 1) * 68 + t] = v.y;
            As[(k + 2) * 68 + t] = v.z; As[(k + 3) * 68 + t] = v.w;
        }
        #pragma unroll
        for (int r = 0; r < 16; r++) {
            int idx = tid + r * 256, k = idx >> 6, c4 = idx & 63;
            *(float4*)&Ws[k * 256 + c4 * 4] = *(const float4*)(W + (size_t)(kc * 64 + k) * M + m0 + c4 * 4);
        }
        __syncthreads();
        #pragma unroll 2
        for (int k = 0; k < 64; k++) {
            const float* xr = &As[k * 68 + tb];
            float4 x0 = *(const float4*)xr, x1 = *(const float4*)(xr + 4);
            const float* wr = &Ws[k * 256 + lane];
            #pragma unroll
            for (int j = 0; j < 8; j++) {
                float w = wr[j * 32];
                acc[0][j] += x0.x * w; acc[1][j] += x0.y * w;
                acc[2][j] += x0.z * w; acc[3][j] += x0.w * w;
                acc[4][j] += x1.x * w; acc[5][j] += x1.y * w;
                acc[6][j] += x1.z * w; acc[7][j] += x1.w * w;
            }
        }
    }
    #pragma unroll
    for (int j = 0; j < 8; j++) {
        int col = m0 + j * 32 + lane;
        float bv = bias[col];
        #pragma unroll
        for (int i = 0; i < 8; i++) {
            float v = acc[i][j] + bv;
            if (RELU) v = fmaxf(v, 0.0f);
            Cout[(size_t)(n0 + tb + i) * M + col] = v;
        }
    }
}

__global__ void __launch_bounds__(NT_)
gate_update_kernel(float* __restrict__ result, const float* __restrict__ out,
                   float* __restrict__ S, const float* __restrict__ Wog,
                   const float* __restrict__ bog, float thresh)
{
    const int lane = threadIdx.x & 31, wid = threadIdx.x >> 5;
    const int b = blockIdx.x * 8 + wid;
    float s = 0.0f;
    if (out) s = S[b];
    const bool da = (out != nullptr) && (s != 0.0f);
    float* row = result + (size_t)b * CO_;
    const float* orow = da ? (out + (size_t)b * CO_) : nullptr;
    float l0 = 0.0f, l1 = 0.0f;
    for (int k = lane * 4; k < CO_; k += 128) {
        float4 r = *(const float4*)&row[k];
        if (da) {
            float4 o = *(const float4*)&orow[k];
            r.x += o.x * s; r.y += o.y * s; r.z += o.z * s; r.w += o.w * s;
            *(float4*)&row[k] = r;
        }
        float4 wA = *(const float4*)&Wog[2 * k];
        float4 wB = *(const float4*)&Wog[2 * k + 4];
        l0 += r.x * wA.x + r.y * wA.z + r.z * wB.x + r.w * wB.z;
        l1 += r.x * wA.y + r.y * wA.w + r.z * wB.y + r.w * wB.w;
    }
    #pragma unroll
    for (int off = 16; off; off >>= 1) {
        l0 += __shfl_xor_sync(0xffffffffu, l0, off);
        l1 += __shfl_xor_sync(0xffffffffu, l1, off);
    }
    if (lane == 0) {
        l0 += bog[0]; l1 += bog[1];
        float m = fmaxf(l0, l1);
        float e0 = expf(l0 - m), e1 = expf(l1 - m);
        float co0 = e0 / (e0 + e1);
        S[b] = (co0 > thresh) ? co0 : 0.0f;
    }
}

__global__ void __launch_bounds__(NT_)
qhead_kernel(const float* __restrict__ hq, const float* __restrict__ Wq2,
             const float* __restrict__ bq2, float* __restrict__ outv)
{
    __shared__ float W2s[HQ_ * AQ_];
    const int tid = threadIdx.x;
    for (int i = tid; i < HQ_ * AQ_; i += NT_) W2s[i] = Wq2[i];
    __syncthreads();
    const int lane = tid & 31, wid = tid >> 5;
    const int b = blockIdx.x * 8 + wid;
    const float* row = hq + (size_t)b * HQ_;
    float acc[AQ_];
    #pragma unroll
    for (int a = 0; a < AQ_; a++) acc[a] = 0.0f;
    for (int k = lane; k < HQ_; k += 32) {
        float v = row[k];
        const float* wr = &W2s[k * AQ_];
        #pragma unroll
        for (int a = 0; a < AQ_; a++) acc[a] += v * wr[a];
    }
    #pragma unroll
    for (int a = 0; a < AQ_; a++)
        #pragma unroll
        for (int off = 16; off; off >>= 1)
            acc[a] += __shfl_xor_sync(0xffffffffu, acc[a], off);
    if (lane == 0) {
        #pragma unroll
        for (int a = 0; a < AQ_; a++) outv[(size_t)b * AQ_ + a] = acc[a] + bq2[a];
    }
}

// ---------------- launch ----------------
extern "C" void kernel_launch(void* const* d_in, const int* in_sizes, int n_in,
                              void* d_out, int out_size)
{
    const float* data = (const float*)d_in[0];
    const float* We1  = (const float*)d_in[1];
    const float* be1  = (const float*)d_in[2];
    const float* We2  = (const float*)d_in[3];
    const float* be2  = (const float*)d_in[4];
    const float* Wg   = (const float*)d_in[5];
    const float* bg   = (const float*)d_in[6];
    const float* Wog  = (const float*)d_in[7];
    const float* bog  = (const float*)d_in[8];
    const float* Wr   = (const float*)d_in[9];
    const float* br   = (const float*)d_in[10];
    const float* Wq1  = (const float*)d_in[11];
    const float* bq1  = (const float*)d_in[12];
    const float* Wq2  = (const float*)d_in[13];
    const float* bq2  = (const float*)d_in[14];
    float* outp = (float*)d_out;

    cudaFuncSetAttribute(moe_mma_kernel, cudaFuncAttributeMaxDynamicSharedMemorySize, MOE_SMEM);
    cudaFuncSetAttribute(gemm_tile_kernel<false>, cudaFuncAttributeMaxDynamicSharedMemorySize, GEMM_SMEM);
    cudaFuncSetAttribute(gemm_tile_kernel<true>,  cudaFuncAttributeMaxDynamicSharedMemorySize, GEMM_SMEM);

    float *res_p, *out_p, *x2_p, *hq_p, *s_p;
    __nv_bfloat16 *xs_p, *w1_p, *w2_p;
    cudaGetSymbolAddress((void**)&res_p, g_result);
    cudaGetSymbolAddress((void**)&out_p, g_out);
    cudaGetSymbolAddress((void**)&x2_p,  g_x2);
    cudaGetSymbolAddress((void**)&hq_p,  g_hq);
    cudaGetSymbolAddress((void**)&s_p,   g_s);
    cudaGetSymbolAddress((void**)&xs_p,  g_xs);
    cudaGetSymbolAddress((void**)&w1_p,  g_w1t);
    cudaGetSymbolAddress((void**)&w2_p,  g_w2t);

    split_w1_kernel<<<E_ * H_ * D_ / 256, 256>>>(We1);
    split_w2_kernel<<<E_ * O_ * H_ / 256, 256>>>(We2);

    const dim3 moe_grid(N_ / 64);            // 512
    const dim3 sx_grid(N_ * D_ / 4 / 256);   // 8192
    const dim3 rmap_grid(N_ / 64, 1);
    const dim3 hq_grid(B_ / 64, 2);
    const dim3 row_grid(B_ / 8);

    split_x_kernel<<<sx_grid, 256>>>(data, xs_p);
    moe_mma_kernel<<<moe_grid, NT_, MOE_SMEM>>>(data, xs_p, w1_p, w2_p, be1, be2, Wg, bg, res_p, nullptr);
    gate_update_kernel<<<row_grid, NT_>>>(res_p, nullptr, s_p, Wog, bog, 0.3f);

    for (int it = 0; it < 2; it++) {
        gemm_tile_kernel<false><<<rmap_grid, NT_, GEMM_SMEM>>>(res_p, Wr, br, x2_p, O_, D_, s_p);
        split_x_kernel<<<sx_grid, 256>>>(x2_p, xs_p);
        moe_mma_kernel<<<moe_grid, NT_, MOE_SMEM>>>(x2_p, xs_p, w1_p, w2_p, be1, be2, Wg, bg, out_p, s_p);
        gate_update_kernel<<<row_grid, NT_>>>(res_p, out_p, s_p, Wog, bog, 0.5f);
    }

    gemm_tile_kernel<true><<<hq_grid, NT_, GEMM_SMEM>>>(res_p, Wq1, bq1, hq_p, HQ_, HQ_, nullptr);
    qhead_kernel<<<row_grid, NT_>>>(hq_p, Wq2, bq2, outp);

    (void)in_sizes; (void)n_in; (void)out_size;
}